// round 14
// baseline (speedup 1.0000x reference)
#include <cuda_runtime.h>
#include <cuda_fp16.h>
#include <cstdint>
#include <cstddef>

#define BATCH   2
#define NTOK    2048
#define DMODEL  1024
#define HEADS   16
#define HD      64
#define MROWS   (BATCH*NTOK)  // 4096
#define WSZ     ((size_t)DMODEL * DMODEL)
#define CSCALE 0.18033688011112042f   // 0.125 * log2(e)
#define ONES_H2 0x3C003C00u           // fp16x2 {1.0, 1.0}

// ======================= helpers ============================================
__device__ __forceinline__ uint32_t smem_u32(const void* p) {
    uint32_t a;
    asm("{ .reg .u64 t; cvta.to.shared.u64 t, %1; cvt.u32.u64 %0, t; }" : "=r"(a) : "l"(p));
    return a;
}
__device__ __forceinline__ void ldsm_x4(uint32_t r[4], uint32_t a) {
    asm volatile("ldmatrix.sync.aligned.m8n8.x4.shared.b16 {%0,%1,%2,%3}, [%4];"
        : "=r"(r[0]), "=r"(r[1]), "=r"(r[2]), "=r"(r[3]) : "r"(a));
}
__device__ __forceinline__ void ldsm_x4t(uint32_t r[4], uint32_t a) {
    asm volatile("ldmatrix.sync.aligned.m8n8.x4.trans.shared.b16 {%0,%1,%2,%3}, [%4];"
        : "=r"(r[0]), "=r"(r[1]), "=r"(r[2]), "=r"(r[3]) : "r"(a));
}
__device__ __forceinline__ void mma_f16(float* c, const uint32_t* a, uint32_t b0, uint32_t b1) {
    asm volatile("mma.sync.aligned.m16n8k16.row.col.f32.f16.f16.f32 "
        "{%0,%1,%2,%3}, {%4,%5,%6,%7}, {%8,%9}, {%0,%1,%2,%3};"
        : "+f"(c[0]), "+f"(c[1]), "+f"(c[2]), "+f"(c[3])
        : "r"(a[0]), "r"(a[1]), "r"(a[2]), "r"(a[3]), "r"(b0), "r"(b1));
}
__device__ __forceinline__ void cp16(uint32_t sa, const void* g) {
    asm volatile("cp.async.cg.shared.global [%0], [%1], 16;"
        :: "r"(sa), "l"(__cvta_generic_to_global(g)) : "memory");
}
#define CP_COMMIT() asm volatile("cp.async.commit_group;" ::: "memory")
#define CP_WAIT0()  asm volatile("cp.async.wait_group 0;"  ::: "memory")
#define CP_WAIT1()  asm volatile("cp.async.wait_group 1;"  ::: "memory")

__device__ __forceinline__ uint32_t pack2h(float a, float b) {
    uint32_t r;
    asm("cvt.rn.f16x2.f32 %0, %1, %2;" : "=r"(r) : "f"(b), "f"(a));
    return r;
}
__device__ __forceinline__ uint32_t hadd2(uint32_t a, uint32_t b) {
    uint32_t r;
    asm("add.f16x2 %0, %1, %2;" : "=r"(r) : "r"(a), "r"(b));
    return r;
}
__device__ __forceinline__ uint32_t hex2(uint32_t a) {
    uint32_t r;
    asm("ex2.approx.f16x2 %0, %1;" : "=r"(r) : "r"(a));
    return r;
}

// ======================= scratch (device globals) ===========================
__device__ __align__(16) __half g_hpe[MROWS * DMODEL];
__device__ __align__(16) __half g_w[4 * DMODEL * DMODEL];
__device__ __align__(16) __half g_qkv[3 * MROWS * DMODEL];
__device__ __align__(16) __half g_ctx[MROWS * DMODEL];
__device__ __align__(16) __half g_pb[BATCH * NTOK];   // log2-domain bias, fp16
__device__ __align__(16) float g_bias3[3 * DMODEL];
// PE sincos tables: coarse (32*n1*div) and fine (n0*div); float2 = (sin, cos)
__device__ __align__(16) float2 g_t1[64 * 512];
__device__ __align__(16) float2 g_tf[32 * 512];

// ======================= aux kernel: PE tables + pbias + bias pack ==========
// blocks [0,128):   T1[n1][p] = sincos(32*n1*div(2p))   (64*512 elems)
// blocks [128,192): TF[n0][p] = sincos(n0*div(2p))      (32*512 elems)
// blocks [192,208): pbias     blocks [208,220): pack bq|bk|bv
__global__ void aux_kernel(const float* __restrict__ probs,
                           const float* __restrict__ scale,
                           const float* __restrict__ bq, const float* __restrict__ bk,
                           const float* __restrict__ bv,
                           float2* __restrict__ t1, float2* __restrict__ tf,
                           __half* __restrict__ pb, float* __restrict__ b3) {
    const float c1 = -9.210340371976184f / 1024.0f;  // -ln(10000)/D
    int bx = blockIdx.x;
    if (bx < 128) {
        int e = bx * blockDim.x + threadIdx.x;       // < 32768
        int n1 = e >> 9, p = e & 511;
        float div = expf((float)(2 * p) * c1);
        float s, c;
        sincosf(32.0f * (float)n1 * div, &s, &c);
        t1[e] = make_float2(s, c);
    } else if (bx < 192) {
        int e = (bx - 128) * blockDim.x + threadIdx.x;  // < 16384
        int n0 = e >> 9, p = e & 511;
        float div = expf((float)(2 * p) * c1);
        float s, c;
        sincosf((float)n0 * div, &s, &c);
        tf[e] = make_float2(s, c);
    } else if (bx < 208) {
        int i = (bx - 192) * blockDim.x + threadIdx.x;
        if (i < BATCH * NTOK)
            pb[i] = __float2half(scale[0] * log2f(probs[i] + 1e-8f));
    } else {
        int i = (bx - 208) * blockDim.x + threadIdx.x;
        if (i < DMODEL)           b3[i] = bq[i];
        else if (i < 2 * DMODEL)  b3[i] = bk[i - DMODEL];
        else if (i < 3 * DMODEL)  b3[i] = bv[i - 2 * DMODEL];
    }
}

// ======================= prep kernel: hpe (table-based PE) + weights ========
// blocks [0, 2048):     hpe = h + PE via angle-addition identity
// blocks [2048, 6144):  weight fp32 -> fp16 (4 matrices)
#define HPE_BLOCKS (NTOK * DMODEL / 4 / 256)         // 2048
#define W_BLOCKS   (DMODEL * DMODEL / 4 / 256)       // 1024 per matrix
#define PREP_GRID  (HPE_BLOCKS + 4 * W_BLOCKS)
__global__ void prep_kernel(const float* __restrict__ h,
                            const float* __restrict__ Wq, const float* __restrict__ Wk,
                            const float* __restrict__ Wv, const float* __restrict__ Wo,
                            const float2* __restrict__ t1, const float2* __restrict__ tf,
                            __half* __restrict__ hpe, __half* __restrict__ w) {
    int bx = blockIdx.x;
    if (bx < HPE_BLOCKS) {
        int idx = bx * blockDim.x + threadIdx.x;   // float4 index within one batch
        int n  = idx >> 8;                         // token
        int d4 = idx & 255;                        // float4 column
        int p0 = d4 * 2, p1 = d4 * 2 + 1;          // d-pair indices
        int n1 = n >> 5, n0 = n & 31;
        // sin(A+B) = sA*cB + cA*sB ; cos(A+B) = cA*cB - sA*sB  (exact identity)
        float2 a0 = t1[n1 * 512 + p0], b0 = tf[n0 * 512 + p0];
        float2 a1 = t1[n1 * 512 + p1], b1 = tf[n0 * 512 + p1];
        float s0  = a0.x * b0.y + a0.y * b0.x;
        float c0  = a0.y * b0.y - a0.x * b0.x;
        float s1  = a1.x * b1.y + a1.y * b1.x;
        float c1v = a1.y * b1.y - a1.x * b1.x;
        const int BSTRIDE = NTOK * DMODEL / 4;
#pragma unroll
        for (int b = 0; b < BATCH; b++) {
            float4 v = reinterpret_cast<const float4*>(h)[b * BSTRIDE + idx];
            uint32_t p01 = pack2h(v.x + s0, v.y + c0);
            uint32_t p23 = pack2h(v.z + s1, v.w + c1v);
            reinterpret_cast<uint2*>(hpe)[b * BSTRIDE + idx] = make_uint2(p01, p23);
        }
    } else {
        int wb = bx - HPE_BLOCKS;
        int m = wb / W_BLOCKS;
        const float* src = (m == 0) ? Wq : (m == 1) ? Wk : (m == 2) ? Wv : Wo;
        int idx = (wb - m * W_BLOCKS) * blockDim.x + threadIdx.x;
        float4 v = reinterpret_cast<const float4*>(src)[idx];
        uint32_t p01 = pack2h(v.x, v.y);
        uint32_t p23 = pack2h(v.z, v.w);
        size_t base = (size_t)m * (DMODEL * DMODEL / 4);
        reinterpret_cast<uint2*>(w)[base + idx] = make_uint2(p01, p23);
    }
}

// ================= HMMA fp16 GEMM (R13 best: 2-stage, 128x128, 2 CTA/SM) ====
#define GPB 144
#define G_STAGE 36864
#define GEMM_SMEM (2 * G_STAGE)   // 73728

template<bool F32OUT>
__global__ __launch_bounds__(256, 2)
void gemm_cp_kernel(const __half* __restrict__ A, const __half* __restrict__ B,
                    const float* __restrict__ bias,
                    float* __restrict__ Cf, __half* __restrict__ Ch) {
    extern __shared__ __align__(16) char sm[];
    const uint32_t sb = smem_u32(sm);

    const int tid = threadIdx.x, lane = tid & 31, wid = tid >> 5;
    const int wm = wid & 3, wn = wid >> 2;
    const int m0 = blockIdx.y * 128;
    const int ng = blockIdx.x * 128;
    const int mat = ng >> 10;
    const int n0 = ng & 1023;

    const __half* Bm = B + (size_t)mat * WSZ;

    auto load_stage = [&](int stage, int kc) {
        uint32_t st = sb + stage * G_STAGE;
#pragma unroll
        for (int t = 0; t < 4; t++) {
            int u = tid + t * 256;
            int r = u >> 3, s = u & 7;
            uint32_t d = (uint32_t)(r * GPB + s * 16);
            cp16(st + d,          A  + (size_t)(m0 + r) * DMODEL + kc * 64 + s * 8);
            cp16(st + 18432 + d,  Bm + (size_t)(n0 + r) * DMODEL + kc * 64 + s * 8);
        }
    };

    float acc[2][8][4];
#pragma unroll
    for (int mi = 0; mi < 2; mi++)
#pragma unroll
        for (int nj = 0; nj < 8; nj++)
#pragma unroll
            for (int q = 0; q < 4; q++) acc[mi][nj][q] = 0.0f;

    const int lr = (lane & 7) + ((lane >> 3) & 1) * 8;
    const int lk = (lane >> 4) * 8;

    load_stage(0, 0);
    CP_COMMIT();

    for (int kc = 0; kc < 16; kc++) {
        const int cur = kc & 1;
        CP_WAIT0();
        __syncthreads();
        if (kc + 1 < 16) {
            load_stage(cur ^ 1, kc + 1);
            CP_COMMIT();
        }
        const uint32_t st = sb + cur * G_STAGE;
#pragma unroll
        for (int ks = 0; ks < 4; ks++) {
            uint32_t af[2][4];
#pragma unroll
            for (int mi = 0; mi < 2; mi++) {
                uint32_t off = (uint32_t)(wm * 32 + mi * 16 + lr) * GPB + (ks * 16 + lk) * 2;
                ldsm_x4(af[mi], st + off);
            }
#pragma unroll
            for (int np = 0; np < 4; np++) {
                uint32_t off = (uint32_t)(wn * 64 + np * 16 + lr) * GPB + (ks * 16 + lk) * 2;
                uint32_t bf[4];
                ldsm_x4(bf, st + 18432u + off);
#pragma unroll
                for (int mi = 0; mi < 2; mi++) {
                    mma_f16(acc[mi][2 * np],     af[mi], bf[0], bf[2]);
                    mma_f16(acc[mi][2 * np + 1], af[mi], bf[1], bf[3]);
                }
            }
        }
    }

    const float osc = (!F32OUT && mat == 0) ? CSCALE : 1.0f;
#pragma unroll
    for (int mi = 0; mi < 2; mi++) {
        int row = m0 + wm * 32 + mi * 16 + (lane >> 2);
#pragma unroll
        for (int nj = 0; nj < 8; nj++) {
            int col = n0 + wn * 64 + nj * 8 + (lane & 3) * 2;
            float b0 = bias[mat * DMODEL + col], b1 = bias[mat * DMODEL + col + 1];
            float v00 = acc[mi][nj][0] + b0, v01 = acc[mi][nj][1] + b1;
            float v10 = acc[mi][nj][2] + b0, v11 = acc[mi][nj][3] + b1;
            if (F32OUT) {
                *(float2*)(Cf + (size_t)row * DMODEL + col)       = make_float2(v00, v01);
                *(float2*)(Cf + (size_t)(row + 8) * DMODEL + col) = make_float2(v10, v11);
            } else {
                size_t base = (size_t)mat * (MROWS * DMODEL);
                *(uint32_t*)(Ch + base + (size_t)row * DMODEL + col)       = pack2h(v00 * osc, v01 * osc);
                *(uint32_t*)(Ch + base + (size_t)(row + 8) * DMODEL + col) = pack2h(v10 * osc, v11 * osc);
            }
        }
    }
}

// ================= HMMA fp16 flash attention (R13 best config) ==============
#define FL_STAGE 18432
#define FL_SMEM  (92160 + 512)   // 92672
#define NKT (NTOK / 64)          // 32

__global__ __launch_bounds__(256, 2)
void flash_mma_kernel(const __half* __restrict__ Q, const __half* __restrict__ K,
                      const __half* __restrict__ V, const __half* __restrict__ pb,
                      __half* __restrict__ C) {
    extern __shared__ __align__(16) char sm[];
    const uint32_t sb = smem_u32(sm);
    const int tid = threadIdx.x, lane = tid & 31, wid = tid >> 5;
    const int qt = blockIdx.x, hh = blockIdx.y, b = blockIdx.z;
    const int rq0 = b * NTOK + qt * 128;

    auto load_kv = [&](int stage, int kt) {
        uint32_t st = sb + 18432 + stage * FL_STAGE;
        int rk0 = b * NTOK + kt * 64;
#pragma unroll
        for (int t = 0; t < 2; t++) {
            int u = tid + t * 256;
            int r = u >> 3, s = u & 7;
            size_t ga = (size_t)(rk0 + r) * DMODEL + hh * HD + s * 8;
            uint32_t d = (uint32_t)(r * GPB + s * 16);
            cp16(st + d,         K + ga);
            cp16(st + 9216 + d,  V + ga);
        }
        if (tid < 8)
            cp16(sb + 92160 + stage * 128 + tid * 16, pb + rk0 + tid * 8);
    };

#pragma unroll
    for (int t = 0; t < 4; t++) {
        int u = tid + t * 256;
        int r = u >> 3, s = u & 7;
        cp16(sb + (uint32_t)(r * GPB + s * 16),
             Q + (size_t)(rq0 + r) * DMODEL + hh * HD + s * 8);
    }
    load_kv(0, 0);
    CP_COMMIT();
    load_kv(1, 1);
    CP_COMMIT();

    const int lr = (lane & 7) + ((lane >> 3) & 1) * 8;
    const int lk = (lane >> 4) * 8;

    uint32_t qf[4][4];
    float o[8][4];
#pragma unroll
    for (int j = 0; j < 8; j++)
#pragma unroll
        for (int q = 0; q < 4; q++) o[j][q] = 0.0f;
    float osum[4] = {0.0f, 0.0f, 0.0f, 0.0f};
    uint32_t sp0[8], sp1[8];

    for (int kt = 0; kt < NKT; kt++) {
        const int cur = kt & 3;
        if (kt < NKT - 2) { CP_WAIT1(); } else { CP_WAIT0(); }
        __syncthreads();
        if (kt == 0) {
#pragma unroll
            for (int ks = 0; ks < 4; ks++) {
                uint32_t qoff = (uint32_t)(wid * 16 + lr) * GPB + (ks * 16 + lk) * 2;
                ldsm_x4(qf[ks], sb + qoff);
            }
        }
        const uint32_t st = sb + 18432 + cur * FL_STAGE;

        // S-MMA(t)
        float s[8][4];
#pragma unroll
        for (int j = 0; j < 8; j++)
#pragma unroll
            for (int q = 0; q < 4; q++) s[j][q] = 0.0f;

#pragma unroll
        for (int ks = 0; ks < 4; ks++) {
#pragma unroll
            for (int np = 0; np < 4; np++) {
                uint32_t off = (uint32_t)(np * 16 + lr) * GPB + (ks * 16 + lk) * 2;
                uint32_t bf[4];
                ldsm_x4(bf, st + off);
                mma_f16(s[2 * np],     qf[ks], bf[0], bf[2]);
                mma_f16(s[2 * np + 1], qf[ks], bf[1], bf[3]);
            }
        }

        // PV-MMA(t-1)
        if (kt > 0) {
            const uint32_t stv = sb + 18432 + ((kt - 1) & 3) * FL_STAGE + 9216;
#pragma unroll
            for (int ks = 0; ks < 4; ks++) {
                uint32_t ap[4] = {sp0[2 * ks], sp1[2 * ks], sp0[2 * ks + 1], sp1[2 * ks + 1]};
                mma_f16(osum, ap, ONES_H2, ONES_H2);
#pragma unroll
                for (int np = 0; np < 4; np++) {
                    uint32_t off = (uint32_t)(ks * 16 + lr) * GPB + (np * 16 + lk) * 2;
                    uint32_t vf[4];
                    ldsm_x4t(vf, stv + off);
                    mma_f16(o[2 * np],     ap, vf[0], vf[1]);
                    mma_f16(o[2 * np + 1], ap, vf[2], vf[3]);
                }
            }
        }

        // prefetch KV(t+2)
        if (kt + 2 < NKT) {
            load_kv((kt + 2) & 3, kt + 2);
            CP_COMMIT();
        }

        // exp(t)
        const uint32_t* pbp = (const uint32_t*)(sm + 92160 + cur * 128);
#pragma unroll
        for (int j = 0; j < 8; j++) {
            uint32_t pbh2 = pbp[j * 4 + (lane & 3)];
            sp0[j] = hex2(hadd2(pack2h(s[j][0], s[j][1]), pbh2));
            sp1[j] = hex2(hadd2(pack2h(s[j][2], s[j][3]), pbh2));
        }
    }

    // epilogue PV(NKT-1)
    {
        const uint32_t stv = sb + 18432 + ((NKT - 1) & 3) * FL_STAGE + 9216;
#pragma unroll
        for (int ks = 0; ks < 4; ks++) {
            uint32_t ap[4] = {sp0[2 * ks], sp1[2 * ks], sp0[2 * ks + 1], sp1[2 * ks + 1]};
            mma_f16(osum, ap, ONES_H2, ONES_H2);
#pragma unroll
            for (int np = 0; np < 4; np++) {
                uint32_t off = (uint32_t)(ks * 16 + lr) * GPB + (np * 16 + lk) * 2;
                uint32_t vf[4];
                ldsm_x4t(vf, stv + off);
                mma_f16(o[2 * np],     ap, vf[0], vf[1]);
                mma_f16(o[2 * np + 1], ap, vf[2], vf[3]);
            }
        }
    }

    float inv0 = 1.0f / osum[0], inv1 = 1.0f / osum[2];
    int row = rq0 + wid * 16 + (lane >> 2);
#pragma unroll
    for (int j = 0; j < 8; j++) {
        int col = hh * HD + j * 8 + (lane & 3) * 2;
        *(uint32_t*)(C + (size_t)row * DMODEL + col)       = pack2h(o[j][0] * inv0, o[j][1] * inv0);
        *(uint32_t*)(C + (size_t)(row + 8) * DMODEL + col) = pack2h(o[j][2] * inv1, o[j][3] * inv1);
    }
}

// ---------------- launch ----------------------------------------------------
extern "C" void kernel_launch(void* const* d_in, const int* in_sizes, int n_in,
                              void* d_out, int out_size) {
    const float* h     = (const float*)d_in[0];
    const float* probs = (const float*)d_in[1];
    const float* Wq    = (const float*)d_in[2];
    const float* bq    = (const float*)d_in[3];
    const float* Wk    = (const float*)d_in[4];
    const float* bk    = (const float*)d_in[5];
    const float* Wv    = (const float*)d_in[6];
    const float* bv    = (const float*)d_in[7];
    const float* Wo    = (const float*)d_in[8];
    const float* bo    = (const float*)d_in[9];
    const float* pscal = (const float*)d_in[10];
    float* out = (float*)d_out;

    __half *hpe, *w, *qkv, *ctx, *pb;
    float *b3;
    float2 *t1, *tf;
    cudaGetSymbolAddress((void**)&hpe, g_hpe);
    cudaGetSymbolAddress((void**)&w,   g_w);
    cudaGetSymbolAddress((void**)&qkv, g_qkv);
    cudaGetSymbolAddress((void**)&ctx, g_ctx);
    cudaGetSymbolAddress((void**)&pb,  g_pb);
    cudaGetSymbolAddress((void**)&b3,  g_bias3);
    cudaGetSymbolAddress((void**)&t1,  g_t1);
    cudaGetSymbolAddress((void**)&tf,  g_tf);

    cudaFuncSetAttribute(gemm_cp_kernel<false>,
                         cudaFuncAttributeMaxDynamicSharedMemorySize, GEMM_SMEM);
    cudaFuncSetAttribute(gemm_cp_kernel<true>,
                         cudaFuncAttributeMaxDynamicSharedMemorySize, GEMM_SMEM);
    cudaFuncSetAttribute(flash_mma_kernel,
                         cudaFuncAttributeMaxDynamicSharedMemorySize, FL_SMEM);

    // 1. aux: PE tables + pbias + bias pack (49K sincos instead of 1M)
    aux_kernel<<<220, 256>>>(probs, pscal, bq, bk, bv, t1, tf, pb, b3);

    // 2. prep: hpe (table-based, exact identity) + weight conversion
    prep_kernel<<<PREP_GRID, 256>>>(h, Wq, Wk, Wv, Wo, t1, tf, hpe, w);

    // 3. fused QKV projection
    const size_t QKV = (size_t)MROWS * DMODEL;
    dim3 qkvgrid(3 * DMODEL / 128, MROWS / 128);    // (24, 32)
    gemm_cp_kernel<false><<<qkvgrid, 256, GEMM_SMEM>>>(hpe, w, b3, nullptr, qkv);

    // 4. flash attention
    dim3 fgrid(NTOK / 128, HEADS, BATCH);
    flash_mma_kernel<<<fgrid, 256, FL_SMEM>>>(qkv, qkv + QKV, qkv + 2 * QKV, pb, ctx);

    // 5. output projection -> d_out (fp32)
    dim3 ogrid(DMODEL / 128, MROWS / 128);          // (8, 32)
    gemm_cp_kernel<true><<<ogrid, 256, GEMM_SMEM>>>(ctx, w + 3 * WSZ, bo, out, nullptr);
}

// round 15
// speedup vs baseline: 1.0511x; 1.0511x over previous
#include <cuda_runtime.h>
#include <cuda_fp16.h>
#include <cstdint>
#include <cstddef>

#define BATCH   2
#define NTOK    2048
#define DMODEL  1024
#define HEADS   16
#define HD      64
#define MROWS   (BATCH*NTOK)  // 4096
#define WSZ     ((size_t)DMODEL * DMODEL)
#define CSCALE 0.18033688011112042f   // 0.125 * log2(e)
#define ONES_H2 0x3C003C00u           // fp16x2 {1.0, 1.0}

// ======================= helpers ============================================
__device__ __forceinline__ uint32_t smem_u32(const void* p) {
    uint32_t a;
    asm("{ .reg .u64 t; cvta.to.shared.u64 t, %1; cvt.u32.u64 %0, t; }" : "=r"(a) : "l"(p));
    return a;
}
__device__ __forceinline__ void ldsm_x4(uint32_t r[4], uint32_t a) {
    asm volatile("ldmatrix.sync.aligned.m8n8.x4.shared.b16 {%0,%1,%2,%3}, [%4];"
        : "=r"(r[0]), "=r"(r[1]), "=r"(r[2]), "=r"(r[3]) : "r"(a));
}
__device__ __forceinline__ void ldsm_x4t(uint32_t r[4], uint32_t a) {
    asm volatile("ldmatrix.sync.aligned.m8n8.x4.trans.shared.b16 {%0,%1,%2,%3}, [%4];"
        : "=r"(r[0]), "=r"(r[1]), "=r"(r[2]), "=r"(r[3]) : "r"(a));
}
__device__ __forceinline__ void mma_f16(float* c, const uint32_t* a, uint32_t b0, uint32_t b1) {
    asm volatile("mma.sync.aligned.m16n8k16.row.col.f32.f16.f16.f32 "
        "{%0,%1,%2,%3}, {%4,%5,%6,%7}, {%8,%9}, {%0,%1,%2,%3};"
        : "+f"(c[0]), "+f"(c[1]), "+f"(c[2]), "+f"(c[3])
        : "r"(a[0]), "r"(a[1]), "r"(a[2]), "r"(a[3]), "r"(b0), "r"(b1));
}
__device__ __forceinline__ void cp16(uint32_t sa, const void* g) {
    asm volatile("cp.async.cg.shared.global [%0], [%1], 16;"
        :: "r"(sa), "l"(__cvta_generic_to_global(g)) : "memory");
}
#define CP_COMMIT() asm volatile("cp.async.commit_group;" ::: "memory")
#define CP_WAIT0()  asm volatile("cp.async.wait_group 0;"  ::: "memory")

__device__ __forceinline__ uint32_t pack2h(float a, float b) {
    uint32_t r;
    asm("cvt.rn.f16x2.f32 %0, %1, %2;" : "=r"(r) : "f"(b), "f"(a));
    return r;
}
__device__ __forceinline__ uint32_t hadd2(uint32_t a, uint32_t b) {
    uint32_t r;
    asm("add.f16x2 %0, %1, %2;" : "=r"(r) : "r"(a), "r"(b));
    return r;
}
__device__ __forceinline__ uint32_t hex2(uint32_t a) {
    uint32_t r;
    asm("ex2.approx.f16x2 %0, %1;" : "=r"(r) : "r"(a));
    return r;
}

// ======================= scratch (device globals) ===========================
__device__ __align__(16) __half g_hpe[MROWS * DMODEL];
__device__ __align__(16) __half g_w[4 * DMODEL * DMODEL];
__device__ __align__(16) __half g_qkv[3 * MROWS * DMODEL];
__device__ __align__(16) __half g_ctx[MROWS * DMODEL];
__device__ __align__(16) __half g_pb[BATCH * NTOK];   // log2-domain bias, fp16
__device__ __align__(16) float g_bias3[3 * DMODEL];

// ======================= fully merged prep kernel (R13 exact) ===============
#define HPE_BLOCKS (NTOK * DMODEL / 4 / 256)         // 2048
#define W_BLOCKS   (DMODEL * DMODEL / 4 / 256)       // 1024 per matrix
#define PREP_GRID  (HPE_BLOCKS + 4 * W_BLOCKS + 16 + 12)
__global__ void prep_kernel(const float* __restrict__ h,
                            const float* __restrict__ probs,
                            const float* __restrict__ scale,
                            const float* __restrict__ bq, const float* __restrict__ bk,
                            const float* __restrict__ bv,
                            const float* __restrict__ Wq, const float* __restrict__ Wk,
                            const float* __restrict__ Wv, const float* __restrict__ Wo,
                            __half* __restrict__ hpe, __half* __restrict__ w,
                            __half* __restrict__ pb, float* __restrict__ b3) {
    int bx = blockIdx.x;
    if (bx < HPE_BLOCKS) {
        int idx = bx * blockDim.x + threadIdx.x;
        int n = idx >> 8;
        int d = (idx & 255) * 4;
        const float c1 = -9.210340371976184f / 1024.0f;
        float fn = (float)n;
        float div0 = expf((float)d * c1);
        float div1 = expf((float)(d + 2) * c1);
        float s0, c0, s1, c1v;
        sincosf(fn * div0, &s0, &c0);
        sincosf(fn * div1, &s1, &c1v);
        const int BSTRIDE = NTOK * DMODEL / 4;
#pragma unroll
        for (int b = 0; b < BATCH; b++) {
            float4 v = reinterpret_cast<const float4*>(h)[b * BSTRIDE + idx];
            uint32_t p01 = pack2h(v.x + s0, v.y + c0);
            uint32_t p23 = pack2h(v.z + s1, v.w + c1v);
            reinterpret_cast<uint2*>(hpe)[b * BSTRIDE + idx] = make_uint2(p01, p23);
        }
    } else if (bx < HPE_BLOCKS + 4 * W_BLOCKS) {
        int wb = bx - HPE_BLOCKS;
        int m = wb / W_BLOCKS;
        const float* src = (m == 0) ? Wq : (m == 1) ? Wk : (m == 2) ? Wv : Wo;
        int idx = (wb - m * W_BLOCKS) * blockDim.x + threadIdx.x;
        float4 v = reinterpret_cast<const float4*>(src)[idx];
        uint32_t p01 = pack2h(v.x, v.y);
        uint32_t p23 = pack2h(v.z, v.w);
        size_t base = (size_t)m * (DMODEL * DMODEL / 4);
        reinterpret_cast<uint2*>(w)[base + idx] = make_uint2(p01, p23);
    } else if (bx < HPE_BLOCKS + 4 * W_BLOCKS + 16) {
        int i = (bx - HPE_BLOCKS - 4 * W_BLOCKS) * blockDim.x + threadIdx.x;
        if (i < BATCH * NTOK)
            pb[i] = __float2half(scale[0] * log2f(probs[i] + 1e-8f));
    } else {
        int i = (bx - HPE_BLOCKS - 4 * W_BLOCKS - 16) * blockDim.x + threadIdx.x;
        if (i < DMODEL)           b3[i] = bq[i];
        else if (i < 2 * DMODEL)  b3[i] = bk[i - DMODEL];
        else if (i < 3 * DMODEL)  b3[i] = bv[i - 2 * DMODEL];
    }
}

// ================= HMMA fp16 GEMM (R13 best: 2-stage, 128x128, 2 CTA/SM) ====
#define GPB 144
#define G_STAGE 36864
#define GEMM_SMEM (2 * G_STAGE)   // 73728

template<bool F32OUT>
__global__ __launch_bounds__(256, 2)
void gemm_cp_kernel(const __half* __restrict__ A, const __half* __restrict__ B,
                    const float* __restrict__ bias,
                    float* __restrict__ Cf, __half* __restrict__ Ch) {
    extern __shared__ __align__(16) char sm[];
    const uint32_t sb = smem_u32(sm);

    const int tid = threadIdx.x, lane = tid & 31, wid = tid >> 5;
    const int wm = wid & 3, wn = wid >> 2;
    const int m0 = blockIdx.y * 128;
    const int ng = blockIdx.x * 128;
    const int mat = ng >> 10;
    const int n0 = ng & 1023;

    const __half* Bm = B + (size_t)mat * WSZ;

    auto load_stage = [&](int stage, int kc) {
        uint32_t st = sb + stage * G_STAGE;
#pragma unroll
        for (int t = 0; t < 4; t++) {
            int u = tid + t * 256;
            int r = u >> 3, s = u & 7;
            uint32_t d = (uint32_t)(r * GPB + s * 16);
            cp16(st + d,          A  + (size_t)(m0 + r) * DMODEL + kc * 64 + s * 8);
            cp16(st + 18432 + d,  Bm + (size_t)(n0 + r) * DMODEL + kc * 64 + s * 8);
        }
    };

    float acc[2][8][4];
#pragma unroll
    for (int mi = 0; mi < 2; mi++)
#pragma unroll
        for (int nj = 0; nj < 8; nj++)
#pragma unroll
            for (int q = 0; q < 4; q++) acc[mi][nj][q] = 0.0f;

    const int lr = (lane & 7) + ((lane >> 3) & 1) * 8;
    const int lk = (lane >> 4) * 8;

    load_stage(0, 0);
    CP_COMMIT();

    for (int kc = 0; kc < 16; kc++) {
        const int cur = kc & 1;
        CP_WAIT0();
        __syncthreads();
        if (kc + 1 < 16) {
            load_stage(cur ^ 1, kc + 1);
            CP_COMMIT();
        }
        const uint32_t st = sb + cur * G_STAGE;
#pragma unroll
        for (int ks = 0; ks < 4; ks++) {
            uint32_t af[2][4];
#pragma unroll
            for (int mi = 0; mi < 2; mi++) {
                uint32_t off = (uint32_t)(wm * 32 + mi * 16 + lr) * GPB + (ks * 16 + lk) * 2;
                ldsm_x4(af[mi], st + off);
            }
#pragma unroll
            for (int np = 0; np < 4; np++) {
                uint32_t off = (uint32_t)(wn * 64 + np * 16 + lr) * GPB + (ks * 16 + lk) * 2;
                uint32_t bf[4];
                ldsm_x4(bf, st + 18432u + off);
#pragma unroll
                for (int mi = 0; mi < 2; mi++) {
                    mma_f16(acc[mi][2 * np],     af[mi], bf[0], bf[2]);
                    mma_f16(acc[mi][2 * np + 1], af[mi], bf[1], bf[3]);
                }
            }
        }
    }

    const float osc = (!F32OUT && mat == 0) ? CSCALE : 1.0f;
#pragma unroll
    for (int mi = 0; mi < 2; mi++) {
        int row = m0 + wm * 32 + mi * 16 + (lane >> 2);
#pragma unroll
        for (int nj = 0; nj < 8; nj++) {
            int col = n0 + wn * 64 + nj * 8 + (lane & 3) * 2;
            float b0 = bias[mat * DMODEL + col], b1 = bias[mat * DMODEL + col + 1];
            float v00 = acc[mi][nj][0] + b0, v01 = acc[mi][nj][1] + b1;
            float v10 = acc[mi][nj][2] + b0, v11 = acc[mi][nj][3] + b1;
            if (F32OUT) {
                *(float2*)(Cf + (size_t)row * DMODEL + col)       = make_float2(v00, v01);
                *(float2*)(Cf + (size_t)(row + 8) * DMODEL + col) = make_float2(v10, v11);
            } else {
                size_t base = (size_t)mat * (MROWS * DMODEL);
                *(uint32_t*)(Ch + base + (size_t)row * DMODEL + col)       = pack2h(v00 * osc, v01 * osc);
                *(uint32_t*)(Ch + base + (size_t)(row + 8) * DMODEL + col) = pack2h(v10 * osc, v11 * osc);
            }
        }
    }
}

// ================= HMMA fp16 flash attention: 64-row Q, 4 CTA/SM ============
// 128 threads (4 warps), warp owns 16 q-rows; K-tile 64, 2-stage double buffer,
// same-tile softmax (ones-MMA rowsum, no max). 4 independent CTAs per SM to
// desynchronize softmax/MMA phase walls across barrier domains.
// smem: Q [0,9216) | stage s at 9216+s*18432 (K +0, V +9216) | pb at 46080+s*128
#define FL_SMEM  (46080 + 384)   // 46464; x4 CTAs = 185856 < 228KB
#define NKT (NTOK / 64)          // 32

__global__ __launch_bounds__(128, 4)
void flash_mma_kernel(const __half* __restrict__ Q, const __half* __restrict__ K,
                      const __half* __restrict__ V, const __half* __restrict__ pb,
                      __half* __restrict__ C) {
    extern __shared__ __align__(16) char sm[];
    const uint32_t sb = smem_u32(sm);
    const int tid = threadIdx.x, lane = tid & 31, wid = tid >> 5;
    const int qt = blockIdx.x, hh = blockIdx.y, b = blockIdx.z;
    const int rq0 = b * NTOK + qt * 64;

    auto load_kv = [&](int stage, int kt) {
        uint32_t st = sb + 9216 + stage * 18432;
        int rk0 = b * NTOK + kt * 64;
#pragma unroll
        for (int t = 0; t < 4; t++) {
            int u = tid + t * 128;
            int r = u >> 3, s = u & 7;
            size_t ga = (size_t)(rk0 + r) * DMODEL + hh * HD + s * 8;
            uint32_t d = (uint32_t)(r * GPB + s * 16);
            cp16(st + d,         K + ga);
            cp16(st + 9216 + d,  V + ga);
        }
        if (tid < 8)
            cp16(sb + 46080 + stage * 128 + tid * 16, pb + rk0 + tid * 8);
    };

    // Q tile: 64 rows x 8 segs (16B)
#pragma unroll
    for (int t = 0; t < 4; t++) {
        int u = tid + t * 128;
        int r = u >> 3, s = u & 7;
        cp16(sb + (uint32_t)(r * GPB + s * 16),
             Q + (size_t)(rq0 + r) * DMODEL + hh * HD + s * 8);
    }
    load_kv(0, 0);
    CP_COMMIT();

    const int lr = (lane & 7) + ((lane >> 3) & 1) * 8;
    const int lk = (lane >> 4) * 8;

    uint32_t qf[4][4];
    float o[8][4];
#pragma unroll
    for (int j = 0; j < 8; j++)
#pragma unroll
        for (int q = 0; q < 4; q++) o[j][q] = 0.0f;
    float osum[4] = {0.0f, 0.0f, 0.0f, 0.0f};

    for (int kt = 0; kt < NKT; kt++) {
        const int cur = kt & 1;
        CP_WAIT0();
        __syncthreads();
        if (kt == 0) {
#pragma unroll
            for (int ks = 0; ks < 4; ks++) {
                uint32_t qoff = (uint32_t)(wid * 16 + lr) * GPB + (ks * 16 + lk) * 2;
                ldsm_x4(qf[ks], sb + qoff);
            }
        }
        if (kt + 1 < NKT) {
            load_kv(cur ^ 1, kt + 1);
            CP_COMMIT();
        }
        const uint32_t st = sb + 9216 + cur * 18432;

        // S = (Q*c) K^T  (log2-domain)
        float s[8][4];
#pragma unroll
        for (int j = 0; j < 8; j++)
#pragma unroll
            for (int q = 0; q < 4; q++) s[j][q] = 0.0f;

#pragma unroll
        for (int ks = 0; ks < 4; ks++) {
#pragma unroll
            for (int np = 0; np < 4; np++) {
                uint32_t off = (uint32_t)(np * 16 + lr) * GPB + (ks * 16 + lk) * 2;
                uint32_t bf[4];
                ldsm_x4(bf, st + off);
                mma_f16(s[2 * np],     qf[ks], bf[0], bf[2]);
                mma_f16(s[2 * np + 1], qf[ks], bf[1], bf[3]);
            }
        }

        // P = ex2.f16x2(S + pb2)
        const uint32_t* pbp = (const uint32_t*)(sm + 46080 + cur * 128);
        uint32_t sp0[8], sp1[8];
#pragma unroll
        for (int j = 0; j < 8; j++) {
            uint32_t pbh2 = pbp[j * 4 + (lane & 3)];
            sp0[j] = hex2(hadd2(pack2h(s[j][0], s[j][1]), pbh2));
            sp1[j] = hex2(hadd2(pack2h(s[j][2], s[j][3]), pbh2));
        }

        // O += P V ; rowsum += P @ ones
#pragma unroll
        for (int ks = 0; ks < 4; ks++) {
            uint32_t ap[4] = {sp0[2 * ks], sp1[2 * ks], sp0[2 * ks + 1], sp1[2 * ks + 1]};
            mma_f16(osum, ap, ONES_H2, ONES_H2);
#pragma unroll
            for (int np = 0; np < 4; np++) {
                uint32_t off = (uint32_t)(ks * 16 + lr) * GPB + (np * 16 + lk) * 2;
                uint32_t vf[4];
                ldsm_x4t(vf, st + 9216u + off);
                mma_f16(o[2 * np],     ap, vf[0], vf[1]);
                mma_f16(o[2 * np + 1], ap, vf[2], vf[3]);
            }
        }
    }

    // normalize + store
    float inv0 = 1.0f / osum[0], inv1 = 1.0f / osum[2];
    int row = rq0 + wid * 16 + (lane >> 2);
#pragma unroll
    for (int j = 0; j < 8; j++) {
        int col = hh * HD + j * 8 + (lane & 3) * 2;
        *(uint32_t*)(C + (size_t)row * DMODEL + col)       = pack2h(o[j][0] * inv0, o[j][1] * inv0);
        *(uint32_t*)(C + (size_t)(row + 8) * DMODEL + col) = pack2h(o[j][2] * inv1, o[j][3] * inv1);
    }
}

// ---------------- launch ----------------------------------------------------
extern "C" void kernel_launch(void* const* d_in, const int* in_sizes, int n_in,
                              void* d_out, int out_size) {
    const float* h     = (const float*)d_in[0];
    const float* probs = (const float*)d_in[1];
    const float* Wq    = (const float*)d_in[2];
    const float* bq    = (const float*)d_in[3];
    const float* Wk    = (const float*)d_in[4];
    const float* bk    = (const float*)d_in[5];
    const float* Wv    = (const float*)d_in[6];
    const float* bv    = (const float*)d_in[7];
    const float* Wo    = (const float*)d_in[8];
    const float* bo    = (const float*)d_in[9];
    const float* pscal = (const float*)d_in[10];
    float* out = (float*)d_out;

    __half *hpe, *w, *qkv, *ctx, *pb;
    float *b3;
    cudaGetSymbolAddress((void**)&hpe, g_hpe);
    cudaGetSymbolAddress((void**)&w,   g_w);
    cudaGetSymbolAddress((void**)&qkv, g_qkv);
    cudaGetSymbolAddress((void**)&ctx, g_ctx);
    cudaGetSymbolAddress((void**)&pb,  g_pb);
    cudaGetSymbolAddress((void**)&b3,  g_bias3);

    cudaFuncSetAttribute(gemm_cp_kernel<false>,
                         cudaFuncAttributeMaxDynamicSharedMemorySize, GEMM_SMEM);
    cudaFuncSetAttribute(gemm_cp_kernel<true>,
                         cudaFuncAttributeMaxDynamicSharedMemorySize, GEMM_SMEM);
    cudaFuncSetAttribute(flash_mma_kernel,
                         cudaFuncAttributeMaxDynamicSharedMemorySize, FL_SMEM);

    // 1. fully merged prep (R13 exact)
    prep_kernel<<<PREP_GRID, 256>>>(h, probs, pscal, bq, bk, bv,
                                    Wq, Wk, Wv, Wo, hpe, w, pb, b3);

    // 2. fused QKV projection
    const size_t QKV = (size_t)MROWS * DMODEL;
    dim3 qkvgrid(3 * DMODEL / 128, MROWS / 128);    // (24, 32)
    gemm_cp_kernel<false><<<qkvgrid, 256, GEMM_SMEM>>>(hpe, w, b3, nullptr, qkv);

    // 3. flash attention: 64-row tiles, 4 CTA/SM
    dim3 fgrid(NTOK / 64, HEADS, BATCH);            // (32, 16, 2) = 1024 CTAs
    flash_mma_kernel<<<fgrid, 128, FL_SMEM>>>(qkv, qkv + QKV, qkv + 2 * QKV, pb, ctx);

    // 4. output projection -> d_out (fp32)
    dim3 ogrid(DMODEL / 128, MROWS / 128);          // (8, 32)
    gemm_cp_kernel<true><<<ogrid, 256, GEMM_SMEM>>>(ctx, w + 3 * WSZ, bo, out, nullptr);
}

// round 16
// speedup vs baseline: 1.0628x; 1.0111x over previous
#include <cuda_runtime.h>
#include <cuda_fp16.h>
#include <cstdint>
#include <cstddef>

#define BATCH   2
#define NTOK    2048
#define DMODEL  1024
#define HEADS   16
#define HD      64
#define MROWS   (BATCH*NTOK)  // 4096
#define WSZ     ((size_t)DMODEL * DMODEL)
#define CSCALE 0.18033688011112042f   // 0.125 * log2(e)
#define ONES_H2 0x3C003C00u           // fp16x2 {1.0, 1.0}

// ======================= helpers ============================================
__device__ __forceinline__ uint32_t smem_u32(const void* p) {
    uint32_t a;
    asm("{ .reg .u64 t; cvta.to.shared.u64 t, %1; cvt.u32.u64 %0, t; }" : "=r"(a) : "l"(p));
    return a;
}
__device__ __forceinline__ void ldsm_x4(uint32_t r[4], uint32_t a) {
    asm volatile("ldmatrix.sync.aligned.m8n8.x4.shared.b16 {%0,%1,%2,%3}, [%4];"
        : "=r"(r[0]), "=r"(r[1]), "=r"(r[2]), "=r"(r[3]) : "r"(a));
}
__device__ __forceinline__ void ldsm_x4t(uint32_t r[4], uint32_t a) {
    asm volatile("ldmatrix.sync.aligned.m8n8.x4.trans.shared.b16 {%0,%1,%2,%3}, [%4];"
        : "=r"(r[0]), "=r"(r[1]), "=r"(r[2]), "=r"(r[3]) : "r"(a));
}
__device__ __forceinline__ void mma_f16(float* c, const uint32_t* a, uint32_t b0, uint32_t b1) {
    asm volatile("mma.sync.aligned.m16n8k16.row.col.f32.f16.f16.f32 "
        "{%0,%1,%2,%3}, {%4,%5,%6,%7}, {%8,%9}, {%0,%1,%2,%3};"
        : "+f"(c[0]), "+f"(c[1]), "+f"(c[2]), "+f"(c[3])
        : "r"(a[0]), "r"(a[1]), "r"(a[2]), "r"(a[3]), "r"(b0), "r"(b1));
}
__device__ __forceinline__ void cp16(uint32_t sa, const void* g) {
    asm volatile("cp.async.cg.shared.global [%0], [%1], 16;"
        :: "r"(sa), "l"(__cvta_generic_to_global(g)) : "memory");
}
#define CP_COMMIT() asm volatile("cp.async.commit_group;" ::: "memory")
#define CP_WAIT0()  asm volatile("cp.async.wait_group 0;"  ::: "memory")

__device__ __forceinline__ uint32_t pack2h(float a, float b) {
    uint32_t r;
    asm("cvt.rn.f16x2.f32 %0, %1, %2;" : "=r"(r) : "f"(b), "f"(a));
    return r;
}
__device__ __forceinline__ uint32_t hadd2(uint32_t a, uint32_t b) {
    uint32_t r;
    asm("add.f16x2 %0, %1, %2;" : "=r"(r) : "r"(a), "r"(b));
    return r;
}
__device__ __forceinline__ uint32_t hex2(uint32_t a) {
    uint32_t r;
    asm("ex2.approx.f16x2 %0, %1;" : "=r"(r) : "r"(a));
    return r;
}

// ======================= scratch (device globals) ===========================
__device__ __align__(16) __half g_hpe[MROWS * DMODEL];
__device__ __align__(16) __half g_w[4 * DMODEL * DMODEL];
__device__ __align__(16) __half g_qkv[3 * MROWS * DMODEL];
__device__ __align__(16) __half g_ctx[MROWS * DMODEL];
__device__ __align__(16) __half g_pb[BATCH * NTOK];   // log2-domain bias, fp16
__device__ __align__(16) float g_bias3[3 * DMODEL];

// ======================= fully merged prep kernel (R13 exact) ===============
#define HPE_BLOCKS (NTOK * DMODEL / 4 / 256)         // 2048
#define W_BLOCKS   (DMODEL * DMODEL / 4 / 256)       // 1024 per matrix
#define PREP_GRID  (HPE_BLOCKS + 4 * W_BLOCKS + 16 + 12)
__global__ void prep_kernel(const float* __restrict__ h,
                            const float* __restrict__ probs,
                            const float* __restrict__ scale,
                            const float* __restrict__ bq, const float* __restrict__ bk,
                            const float* __restrict__ bv,
                            const float* __restrict__ Wq, const float* __restrict__ Wk,
                            const float* __restrict__ Wv, const float* __restrict__ Wo,
                            __half* __restrict__ hpe, __half* __restrict__ w,
                            __half* __restrict__ pb, float* __restrict__ b3) {
    int bx = blockIdx.x;
    if (bx < HPE_BLOCKS) {
        int idx = bx * blockDim.x + threadIdx.x;
        int n = idx >> 8;
        int d = (idx & 255) * 4;
        const float c1 = -9.210340371976184f / 1024.0f;
        float fn = (float)n;
        float div0 = expf((float)d * c1);
        float div1 = expf((float)(d + 2) * c1);
        float s0, c0, s1, c1v;
        sincosf(fn * div0, &s0, &c0);
        sincosf(fn * div1, &s1, &c1v);
        const int BSTRIDE = NTOK * DMODEL / 4;
#pragma unroll
        for (int b = 0; b < BATCH; b++) {
            float4 v = reinterpret_cast<const float4*>(h)[b * BSTRIDE + idx];
            uint32_t p01 = pack2h(v.x + s0, v.y + c0);
            uint32_t p23 = pack2h(v.z + s1, v.w + c1v);
            reinterpret_cast<uint2*>(hpe)[b * BSTRIDE + idx] = make_uint2(p01, p23);
        }
    } else if (bx < HPE_BLOCKS + 4 * W_BLOCKS) {
        int wb = bx - HPE_BLOCKS;
        int m = wb / W_BLOCKS;
        const float* src = (m == 0) ? Wq : (m == 1) ? Wk : (m == 2) ? Wv : Wo;
        int idx = (wb - m * W_BLOCKS) * blockDim.x + threadIdx.x;
        float4 v = reinterpret_cast<const float4*>(src)[idx];
        uint32_t p01 = pack2h(v.x, v.y);
        uint32_t p23 = pack2h(v.z, v.w);
        size_t base = (size_t)m * (DMODEL * DMODEL / 4);
        reinterpret_cast<uint2*>(w)[base + idx] = make_uint2(p01, p23);
    } else if (bx < HPE_BLOCKS + 4 * W_BLOCKS + 16) {
        int i = (bx - HPE_BLOCKS - 4 * W_BLOCKS) * blockDim.x + threadIdx.x;
        if (i < BATCH * NTOK)
            pb[i] = __float2half(scale[0] * log2f(probs[i] + 1e-8f));
    } else {
        int i = (bx - HPE_BLOCKS - 4 * W_BLOCKS - 16) * blockDim.x + threadIdx.x;
        if (i < DMODEL)           b3[i] = bq[i];
        else if (i < 2 * DMODEL)  b3[i] = bk[i - DMODEL];
        else if (i < 3 * DMODEL)  b3[i] = bv[i - 2 * DMODEL];
    }
}

// ================= HMMA fp16 GEMM: 64x128 CTA tile, 4 CTA/SM ================
// 128 threads (4 warps, 2x2 grid), warp tile 32x64, K-chunk 64, 2-stage.
// smem stage: 64 A-rows @0 (9216B) + 128 B-rows @9216 (18432B) = 27648.
#define GPB 144
#define G_STAGE 27648
#define G_BOFF  9216
#define GEMM_SMEM (2 * G_STAGE)   // 55296; x4 CTAs = 221184 < 228KB

template<bool F32OUT>
__global__ __launch_bounds__(128, 4)
void gemm_cp_kernel(const __half* __restrict__ A, const __half* __restrict__ B,
                    const float* __restrict__ bias,
                    float* __restrict__ Cf, __half* __restrict__ Ch) {
    extern __shared__ __align__(16) char sm[];
    const uint32_t sb = smem_u32(sm);

    const int tid = threadIdx.x, lane = tid & 31, wid = tid >> 5;
    const int wm = wid & 1, wn = wid >> 1;        // 2 x 2 warp grid
    const int m0 = blockIdx.y * 64;
    const int ng = blockIdx.x * 128;
    const int mat = ng >> 10;
    const int n0 = ng & 1023;

    const __half* Bm = B + (size_t)mat * WSZ;

    auto load_stage = [&](int stage, int kc) {
        uint32_t st = sb + stage * G_STAGE;
#pragma unroll
        for (int t = 0; t < 4; t++) {          // A: 64 rows x 8 segs = 512 units
            int u = tid + t * 128;
            int r = u >> 3, s = u & 7;
            cp16(st + (uint32_t)(r * GPB + s * 16),
                 A + (size_t)(m0 + r) * DMODEL + kc * 64 + s * 8);
        }
#pragma unroll
        for (int t = 0; t < 8; t++) {          // B: 128 rows x 8 segs = 1024 units
            int u = tid + t * 128;
            int r = u >> 3, s = u & 7;
            cp16(st + G_BOFF + (uint32_t)(r * GPB + s * 16),
                 Bm + (size_t)(n0 + r) * DMODEL + kc * 64 + s * 8);
        }
    };

    float acc[2][8][4];
#pragma unroll
    for (int mi = 0; mi < 2; mi++)
#pragma unroll
        for (int nj = 0; nj < 8; nj++)
#pragma unroll
            for (int q = 0; q < 4; q++) acc[mi][nj][q] = 0.0f;

    const int lr = (lane & 7) + ((lane >> 3) & 1) * 8;
    const int lk = (lane >> 4) * 8;

    load_stage(0, 0);
    CP_COMMIT();

    for (int kc = 0; kc < 16; kc++) {
        const int cur = kc & 1;
        CP_WAIT0();
        __syncthreads();
        if (kc + 1 < 16) {
            load_stage(cur ^ 1, kc + 1);
            CP_COMMIT();
        }
        const uint32_t st = sb + cur * G_STAGE;
#pragma unroll
        for (int ks = 0; ks < 4; ks++) {
            uint32_t af[2][4];
#pragma unroll
            for (int mi = 0; mi < 2; mi++) {
                uint32_t off = (uint32_t)(wm * 32 + mi * 16 + lr) * GPB + (ks * 16 + lk) * 2;
                ldsm_x4(af[mi], st + off);
            }
#pragma unroll
            for (int np = 0; np < 4; np++) {
                uint32_t off = G_BOFF + (uint32_t)(wn * 64 + np * 16 + lr) * GPB + (ks * 16 + lk) * 2;
                uint32_t bf[4];
                ldsm_x4(bf, st + off);
#pragma unroll
                for (int mi = 0; mi < 2; mi++) {
                    mma_f16(acc[mi][2 * np],     af[mi], bf[0], bf[2]);
                    mma_f16(acc[mi][2 * np + 1], af[mi], bf[1], bf[3]);
                }
            }
        }
    }

    const float osc = (!F32OUT && mat == 0) ? CSCALE : 1.0f;
#pragma unroll
    for (int mi = 0; mi < 2; mi++) {
        int row = m0 + wm * 32 + mi * 16 + (lane >> 2);
#pragma unroll
        for (int nj = 0; nj < 8; nj++) {
            int col = n0 + wn * 64 + nj * 8 + (lane & 3) * 2;
            float b0 = bias[mat * DMODEL + col], b1 = bias[mat * DMODEL + col + 1];
            float v00 = acc[mi][nj][0] + b0, v01 = acc[mi][nj][1] + b1;
            float v10 = acc[mi][nj][2] + b0, v11 = acc[mi][nj][3] + b1;
            if (F32OUT) {
                *(float2*)(Cf + (size_t)row * DMODEL + col)       = make_float2(v00, v01);
                *(float2*)(Cf + (size_t)(row + 8) * DMODEL + col) = make_float2(v10, v11);
            } else {
                size_t base = (size_t)mat * (MROWS * DMODEL);
                *(uint32_t*)(Ch + base + (size_t)row * DMODEL + col)       = pack2h(v00 * osc, v01 * osc);
                *(uint32_t*)(Ch + base + (size_t)(row + 8) * DMODEL + col) = pack2h(v10 * osc, v11 * osc);
            }
        }
    }
}

// ================= HMMA fp16 flash attention (R15 best: 64-row, 4 CTA/SM) ===
#define FL_SMEM  (46080 + 384)   // 46464; x4 CTAs = 185856 < 228KB
#define NKT (NTOK / 64)          // 32

__global__ __launch_bounds__(128, 4)
void flash_mma_kernel(const __half* __restrict__ Q, const __half* __restrict__ K,
                      const __half* __restrict__ V, const __half* __restrict__ pb,
                      __half* __restrict__ C) {
    extern __shared__ __align__(16) char sm[];
    const uint32_t sb = smem_u32(sm);
    const int tid = threadIdx.x, lane = tid & 31, wid = tid >> 5;
    const int qt = blockIdx.x, hh = blockIdx.y, b = blockIdx.z;
    const int rq0 = b * NTOK + qt * 64;

    auto load_kv = [&](int stage, int kt) {
        uint32_t st = sb + 9216 + stage * 18432;
        int rk0 = b * NTOK + kt * 64;
#pragma unroll
        for (int t = 0; t < 4; t++) {
            int u = tid + t * 128;
            int r = u >> 3, s = u & 7;
            size_t ga = (size_t)(rk0 + r) * DMODEL + hh * HD + s * 8;
            uint32_t d = (uint32_t)(r * GPB + s * 16);
            cp16(st + d,         K + ga);
            cp16(st + 9216 + d,  V + ga);
        }
        if (tid < 8)
            cp16(sb + 46080 + stage * 128 + tid * 16, pb + rk0 + tid * 8);
    };

    // Q tile: 64 rows x 8 segs (16B)
#pragma unroll
    for (int t = 0; t < 4; t++) {
        int u = tid + t * 128;
        int r = u >> 3, s = u & 7;
        cp16(sb + (uint32_t)(r * GPB + s * 16),
             Q + (size_t)(rq0 + r) * DMODEL + hh * HD + s * 8);
    }
    load_kv(0, 0);
    CP_COMMIT();

    const int lr = (lane & 7) + ((lane >> 3) & 1) * 8;
    const int lk = (lane >> 4) * 8;

    uint32_t qf[4][4];
    float o[8][4];
#pragma unroll
    for (int j = 0; j < 8; j++)
#pragma unroll
        for (int q = 0; q < 4; q++) o[j][q] = 0.0f;
    float osum[4] = {0.0f, 0.0f, 0.0f, 0.0f};

    for (int kt = 0; kt < NKT; kt++) {
        const int cur = kt & 1;
        CP_WAIT0();
        __syncthreads();
        if (kt == 0) {
#pragma unroll
            for (int ks = 0; ks < 4; ks++) {
                uint32_t qoff = (uint32_t)(wid * 16 + lr) * GPB + (ks * 16 + lk) * 2;
                ldsm_x4(qf[ks], sb + qoff);
            }
        }
        if (kt + 1 < NKT) {
            load_kv(cur ^ 1, kt + 1);
            CP_COMMIT();
        }
        const uint32_t st = sb + 9216 + cur * 18432;

        // S = (Q*c) K^T  (log2-domain)
        float s[8][4];
#pragma unroll
        for (int j = 0; j < 8; j++)
#pragma unroll
            for (int q = 0; q < 4; q++) s[j][q] = 0.0f;

#pragma unroll
        for (int ks = 0; ks < 4; ks++) {
#pragma unroll
            for (int np = 0; np < 4; np++) {
                uint32_t off = (uint32_t)(np * 16 + lr) * GPB + (ks * 16 + lk) * 2;
                uint32_t bf[4];
                ldsm_x4(bf, st + off);
                mma_f16(s[2 * np],     qf[ks], bf[0], bf[2]);
                mma_f16(s[2 * np + 1], qf[ks], bf[1], bf[3]);
            }
        }

        // P = ex2.f16x2(S + pb2)
        const uint32_t* pbp = (const uint32_t*)(sm + 46080 + cur * 128);
        uint32_t sp0[8], sp1[8];
#pragma unroll
        for (int j = 0; j < 8; j++) {
            uint32_t pbh2 = pbp[j * 4 + (lane & 3)];
            sp0[j] = hex2(hadd2(pack2h(s[j][0], s[j][1]), pbh2));
            sp1[j] = hex2(hadd2(pack2h(s[j][2], s[j][3]), pbh2));
        }

        // O += P V ; rowsum += P @ ones
#pragma unroll
        for (int ks = 0; ks < 4; ks++) {
            uint32_t ap[4] = {sp0[2 * ks], sp1[2 * ks], sp0[2 * ks + 1], sp1[2 * ks + 1]};
            mma_f16(osum, ap, ONES_H2, ONES_H2);
#pragma unroll
            for (int np = 0; np < 4; np++) {
                uint32_t off = (uint32_t)(ks * 16 + lr) * GPB + (np * 16 + lk) * 2;
                uint32_t vf[4];
                ldsm_x4t(vf, st + 9216u + off);
                mma_f16(o[2 * np],     ap, vf[0], vf[1]);
                mma_f16(o[2 * np + 1], ap, vf[2], vf[3]);
            }
        }
    }

    // normalize + store
    float inv0 = 1.0f / osum[0], inv1 = 1.0f / osum[2];
    int row = rq0 + wid * 16 + (lane >> 2);
#pragma unroll
    for (int j = 0; j < 8; j++) {
        int col = hh * HD + j * 8 + (lane & 3) * 2;
        *(uint32_t*)(C + (size_t)row * DMODEL + col)       = pack2h(o[j][0] * inv0, o[j][1] * inv0);
        *(uint32_t*)(C + (size_t)(row + 8) * DMODEL + col) = pack2h(o[j][2] * inv1, o[j][3] * inv1);
    }
}

// ---------------- launch ----------------------------------------------------
extern "C" void kernel_launch(void* const* d_in, const int* in_sizes, int n_in,
                              void* d_out, int out_size) {
    const float* h     = (const float*)d_in[0];
    const float* probs = (const float*)d_in[1];
    const float* Wq    = (const float*)d_in[2];
    const float* bq    = (const float*)d_in[3];
    const float* Wk    = (const float*)d_in[4];
    const float* bk    = (const float*)d_in[5];
    const float* Wv    = (const float*)d_in[6];
    const float* bv    = (const float*)d_in[7];
    const float* Wo    = (const float*)d_in[8];
    const float* bo    = (const float*)d_in[9];
    const float* pscal = (const float*)d_in[10];
    float* out = (float*)d_out;

    __half *hpe, *w, *qkv, *ctx, *pb;
    float *b3;
    cudaGetSymbolAddress((void**)&hpe, g_hpe);
    cudaGetSymbolAddress((void**)&w,   g_w);
    cudaGetSymbolAddress((void**)&qkv, g_qkv);
    cudaGetSymbolAddress((void**)&ctx, g_ctx);
    cudaGetSymbolAddress((void**)&pb,  g_pb);
    cudaGetSymbolAddress((void**)&b3,  g_bias3);

    cudaFuncSetAttribute(gemm_cp_kernel<false>,
                         cudaFuncAttributeMaxDynamicSharedMemorySize, GEMM_SMEM);
    cudaFuncSetAttribute(gemm_cp_kernel<true>,
                         cudaFuncAttributeMaxDynamicSharedMemorySize, GEMM_SMEM);
    cudaFuncSetAttribute(flash_mma_kernel,
                         cudaFuncAttributeMaxDynamicSharedMemorySize, FL_SMEM);

    // 1. fully merged prep
    prep_kernel<<<PREP_GRID, 256>>>(h, probs, pscal, bq, bk, bv,
                                    Wq, Wk, Wv, Wo, hpe, w, pb, b3);

    // 2. fused QKV projection: 64x128 tiles, 4 CTA/SM
    const size_t QKV = (size_t)MROWS * DMODEL;
    dim3 qkvgrid(3 * DMODEL / 128, MROWS / 64);     // (24, 64) = 1536 CTAs
    gemm_cp_kernel<false><<<qkvgrid, 128, GEMM_SMEM>>>(hpe, w, b3, nullptr, qkv);

    // 3. flash attention (R15 winner)
    dim3 fgrid(NTOK / 64, HEADS, BATCH);            // (32, 16, 2)
    flash_mma_kernel<<<fgrid, 128, FL_SMEM>>>(qkv, qkv + QKV, qkv + 2 * QKV, pb, ctx);

    // 4. output projection -> d_out (fp32): 512 CTAs = single wave at 4 CTA/SM
    dim3 ogrid(DMODEL / 128, MROWS / 64);           // (8, 64)
    gemm_cp_kernel<true><<<ogrid, 128, GEMM_SMEM>>>(ctx, w + 3 * WSZ, bo, out, nullptr);
}

// round 17
// speedup vs baseline: 1.0694x; 1.0062x over previous
#include <cuda_runtime.h>
#include <cuda_fp16.h>
#include <cstdint>
#include <cstddef>

#define BATCH   2
#define NTOK    2048
#define DMODEL  1024
#define HEADS   16
#define HD      64
#define MROWS   (BATCH*NTOK)  // 4096
#define WSZ     ((size_t)DMODEL * DMODEL)
#define CSCALE 0.18033688011112042f   // 0.125 * log2(e)
#define ONES_H2 0x3C003C00u           // fp16x2 {1.0, 1.0}

// ======================= helpers ============================================
__device__ __forceinline__ uint32_t smem_u32(const void* p) {
    uint32_t a;
    asm("{ .reg .u64 t; cvta.to.shared.u64 t, %1; cvt.u32.u64 %0, t; }" : "=r"(a) : "l"(p));
    return a;
}
__device__ __forceinline__ void ldsm_x4(uint32_t r[4], uint32_t a) {
    asm volatile("ldmatrix.sync.aligned.m8n8.x4.shared.b16 {%0,%1,%2,%3}, [%4];"
        : "=r"(r[0]), "=r"(r[1]), "=r"(r[2]), "=r"(r[3]) : "r"(a));
}
__device__ __forceinline__ void ldsm_x4t(uint32_t r[4], uint32_t a) {
    asm volatile("ldmatrix.sync.aligned.m8n8.x4.trans.shared.b16 {%0,%1,%2,%3}, [%4];"
        : "=r"(r[0]), "=r"(r[1]), "=r"(r[2]), "=r"(r[3]) : "r"(a));
}
__device__ __forceinline__ void mma_f16(float* c, const uint32_t* a, uint32_t b0, uint32_t b1) {
    asm volatile("mma.sync.aligned.m16n8k16.row.col.f32.f16.f16.f32 "
        "{%0,%1,%2,%3}, {%4,%5,%6,%7}, {%8,%9}, {%0,%1,%2,%3};"
        : "+f"(c[0]), "+f"(c[1]), "+f"(c[2]), "+f"(c[3])
        : "r"(a[0]), "r"(a[1]), "r"(a[2]), "r"(a[3]), "r"(b0), "r"(b1));
}
__device__ __forceinline__ void cp16(uint32_t sa, const void* g) {
    asm volatile("cp.async.cg.shared.global [%0], [%1], 16;"
        :: "r"(sa), "l"(__cvta_generic_to_global(g)) : "memory");
}
#define CP_COMMIT() asm volatile("cp.async.commit_group;" ::: "memory")
#define CP_WAIT0()  asm volatile("cp.async.wait_group 0;"  ::: "memory")

__device__ __forceinline__ uint32_t pack2h(float a, float b) {
    uint32_t r;
    asm("cvt.rn.f16x2.f32 %0, %1, %2;" : "=r"(r) : "f"(b), "f"(a));
    return r;
}
__device__ __forceinline__ uint32_t hadd2(uint32_t a, uint32_t b) {
    uint32_t r;
    asm("add.f16x2 %0, %1, %2;" : "=r"(r) : "r"(a), "r"(b));
    return r;
}
__device__ __forceinline__ uint32_t hex2(uint32_t a) {
    uint32_t r;
    asm("ex2.approx.f16x2 %0, %1;" : "=r"(r) : "r"(a));
    return r;
}

// ======================= scratch (device globals) ===========================
__device__ __align__(16) __half g_hpe[MROWS * DMODEL];
__device__ __align__(16) __half g_w[4 * DMODEL * DMODEL];
__device__ __align__(16) __half g_qkv[3 * MROWS * DMODEL];
__device__ __align__(16) __half g_ctx[MROWS * DMODEL];
__device__ __align__(16) __half g_pb[BATCH * NTOK];
__device__ __align__(16) float g_bias3[3 * DMODEL];

// ======================= fully merged prep kernel (R13 exact) ===============
#define HPE_BLOCKS (NTOK * DMODEL / 4 / 256)         // 2048
#define W_BLOCKS   (DMODEL * DMODEL / 4 / 256)       // 1024 per matrix
#define PREP_GRID  (HPE_BLOCKS + 4 * W_BLOCKS + 16 + 12)
__global__ void prep_kernel(const float* __restrict__ h,
                            const float* __restrict__ probs,
                            const float* __restrict__ scale,
                            const float* __restrict__ bq, const float* __restrict__ bk,
                            const float* __restrict__ bv,
                            const float* __restrict__ Wq, const float* __restrict__ Wk,
                            const float* __restrict__ Wv, const float* __restrict__ Wo,
                            __half* __restrict__ hpe, __half* __restrict__ w,
                            __half* __restrict__ pb, float* __restrict__ b3) {
    int bx = blockIdx.x;
    if (bx < HPE_BLOCKS) {
        int idx = bx * blockDim.x + threadIdx.x;
        int n = idx >> 8;
        int d = (idx & 255) * 4;
        const float c1 = -9.210340371976184f / 1024.0f;
        float fn = (float)n;
        float div0 = expf((float)d * c1);
        float div1 = expf((float)(d + 2) * c1);
        float s0, c0, s1, c1v;
        sincosf(fn * div0, &s0, &c0);
        sincosf(fn * div1, &s1, &c1v);
        const int BSTRIDE = NTOK * DMODEL / 4;
#pragma unroll
        for (int b = 0; b < BATCH; b++) {
            float4 v = reinterpret_cast<const float4*>(h)[b * BSTRIDE + idx];
            uint32_t p01 = pack2h(v.x + s0, v.y + c0);
            uint32_t p23 = pack2h(v.z + s1, v.w + c1v);
            reinterpret_cast<uint2*>(hpe)[b * BSTRIDE + idx] = make_uint2(p01, p23);
        }
    } else if (bx < HPE_BLOCKS + 4 * W_BLOCKS) {
        int wb = bx - HPE_BLOCKS;
        int m = wb / W_BLOCKS;
        const float* src = (m == 0) ? Wq : (m == 1) ? Wk : (m == 2) ? Wv : Wo;
        int idx = (wb - m * W_BLOCKS) * blockDim.x + threadIdx.x;
        float4 v = reinterpret_cast<const float4*>(src)[idx];
        uint32_t p01 = pack2h(v.x, v.y);
        uint32_t p23 = pack2h(v.z, v.w);
        size_t base = (size_t)m * (DMODEL * DMODEL / 4);
        reinterpret_cast<uint2*>(w)[base + idx] = make_uint2(p01, p23);
    } else if (bx < HPE_BLOCKS + 4 * W_BLOCKS + 16) {
        int i = (bx - HPE_BLOCKS - 4 * W_BLOCKS) * blockDim.x + threadIdx.x;
        if (i < BATCH * NTOK)
            pb[i] = __float2half(scale[0] * log2f(probs[i] + 1e-8f));
    } else {
        int i = (bx - HPE_BLOCKS - 4 * W_BLOCKS - 16) * blockDim.x + threadIdx.x;
        if (i < DMODEL)           b3[i] = bq[i];
        else if (i < 2 * DMODEL)  b3[i] = bk[i - DMODEL];
        else if (i < 3 * DMODEL)  b3[i] = bv[i - 2 * DMODEL];
    }
}

#define GPB 144

// ============ QKV GEMM: 64x128 CTA tile, 128 thr, 4 CTA/SM (R16 winner) =====
#define GQ_STAGE 27648
#define GQ_BOFF  9216
#define GQ_SMEM (2 * GQ_STAGE)   // 55296

__global__ __launch_bounds__(128, 4)
void gemm_qkv_kernel(const __half* __restrict__ A, const __half* __restrict__ B,
                     const float* __restrict__ bias, __half* __restrict__ Ch) {
    extern __shared__ __align__(16) char sm[];
    const uint32_t sb = smem_u32(sm);

    const int tid = threadIdx.x, lane = tid & 31, wid = tid >> 5;
    const int wm = wid & 1, wn = wid >> 1;
    const int m0 = blockIdx.y * 64;
    const int ng = blockIdx.x * 128;
    const int mat = ng >> 10;
    const int n0 = ng & 1023;

    const __half* Bm = B + (size_t)mat * WSZ;

    auto load_stage = [&](int stage, int kc) {
        uint32_t st = sb + stage * GQ_STAGE;
#pragma unroll
        for (int t = 0; t < 4; t++) {
            int u = tid + t * 128;
            int r = u >> 3, s = u & 7;
            cp16(st + (uint32_t)(r * GPB + s * 16),
                 A + (size_t)(m0 + r) * DMODEL + kc * 64 + s * 8);
        }
#pragma unroll
        for (int t = 0; t < 8; t++) {
            int u = tid + t * 128;
            int r = u >> 3, s = u & 7;
            cp16(st + GQ_BOFF + (uint32_t)(r * GPB + s * 16),
                 Bm + (size_t)(n0 + r) * DMODEL + kc * 64 + s * 8);
        }
    };

    float acc[2][8][4];
#pragma unroll
    for (int mi = 0; mi < 2; mi++)
#pragma unroll
        for (int nj = 0; nj < 8; nj++)
#pragma unroll
            for (int q = 0; q < 4; q++) acc[mi][nj][q] = 0.0f;

    const int lr = (lane & 7) + ((lane >> 3) & 1) * 8;
    const int lk = (lane >> 4) * 8;

    load_stage(0, 0);
    CP_COMMIT();

    for (int kc = 0; kc < 16; kc++) {
        const int cur = kc & 1;
        CP_WAIT0();
        __syncthreads();
        if (kc + 1 < 16) {
            load_stage(cur ^ 1, kc + 1);
            CP_COMMIT();
        }
        const uint32_t st = sb + cur * GQ_STAGE;
#pragma unroll
        for (int ks = 0; ks < 4; ks++) {
            uint32_t af[2][4];
#pragma unroll
            for (int mi = 0; mi < 2; mi++) {
                uint32_t off = (uint32_t)(wm * 32 + mi * 16 + lr) * GPB + (ks * 16 + lk) * 2;
                ldsm_x4(af[mi], st + off);
            }
#pragma unroll
            for (int np = 0; np < 4; np++) {
                uint32_t off = GQ_BOFF + (uint32_t)(wn * 64 + np * 16 + lr) * GPB + (ks * 16 + lk) * 2;
                uint32_t bf[4];
                ldsm_x4(bf, st + off);
#pragma unroll
                for (int mi = 0; mi < 2; mi++) {
                    mma_f16(acc[mi][2 * np],     af[mi], bf[0], bf[2]);
                    mma_f16(acc[mi][2 * np + 1], af[mi], bf[1], bf[3]);
                }
            }
        }
    }

    const float osc = (mat == 0) ? CSCALE : 1.0f;
    size_t base = (size_t)mat * (MROWS * DMODEL);
#pragma unroll
    for (int mi = 0; mi < 2; mi++) {
        int row = m0 + wm * 32 + mi * 16 + (lane >> 2);
#pragma unroll
        for (int nj = 0; nj < 8; nj++) {
            int col = n0 + wn * 64 + nj * 8 + (lane & 3) * 2;
            float b0 = bias[mat * DMODEL + col], b1 = bias[mat * DMODEL + col + 1];
            float v00 = acc[mi][nj][0] + b0, v01 = acc[mi][nj][1] + b1;
            float v10 = acc[mi][nj][2] + b0, v11 = acc[mi][nj][3] + b1;
            *(uint32_t*)(Ch + base + (size_t)row * DMODEL + col)       = pack2h(v00 * osc, v01 * osc);
            *(uint32_t*)(Ch + base + (size_t)(row + 8) * DMODEL + col) = pack2h(v10 * osc, v11 * osc);
        }
    }
}

// ============ OUT GEMM: 128x128 CTA tile, 256 thr, 2 CTA/SM (R13 winner) ====
#define GO_STAGE 36864
#define GO_SMEM (2 * GO_STAGE)   // 73728

__global__ __launch_bounds__(256, 2)
void gemm_out_kernel(const __half* __restrict__ A, const __half* __restrict__ B,
                     const float* __restrict__ bias, float* __restrict__ Cf) {
    extern __shared__ __align__(16) char sm[];
    const uint32_t sb = smem_u32(sm);

    const int tid = threadIdx.x, lane = tid & 31, wid = tid >> 5;
    const int wm = wid & 3, wn = wid >> 2;
    const int m0 = blockIdx.y * 128;
    const int n0 = blockIdx.x * 128;

    auto load_stage = [&](int stage, int kc) {
        uint32_t st = sb + stage * GO_STAGE;
#pragma unroll
        for (int t = 0; t < 4; t++) {
            int u = tid + t * 256;
            int r = u >> 3, s = u & 7;
            uint32_t d = (uint32_t)(r * GPB + s * 16);
            cp16(st + d,          A + (size_t)(m0 + r) * DMODEL + kc * 64 + s * 8);
            cp16(st + 18432 + d,  B + (size_t)(n0 + r) * DMODEL + kc * 64 + s * 8);
        }
    };

    float acc[2][8][4];
#pragma unroll
    for (int mi = 0; mi < 2; mi++)
#pragma unroll
        for (int nj = 0; nj < 8; nj++)
#pragma unroll
            for (int q = 0; q < 4; q++) acc[mi][nj][q] = 0.0f;

    const int lr = (lane & 7) + ((lane >> 3) & 1) * 8;
    const int lk = (lane >> 4) * 8;

    load_stage(0, 0);
    CP_COMMIT();

    for (int kc = 0; kc < 16; kc++) {
        const int cur = kc & 1;
        CP_WAIT0();
        __syncthreads();
        if (kc + 1 < 16) {
            load_stage(cur ^ 1, kc + 1);
            CP_COMMIT();
        }
        const uint32_t st = sb + cur * GO_STAGE;
#pragma unroll
        for (int ks = 0; ks < 4; ks++) {
            uint32_t af[2][4];
#pragma unroll
            for (int mi = 0; mi < 2; mi++) {
                uint32_t off = (uint32_t)(wm * 32 + mi * 16 + lr) * GPB + (ks * 16 + lk) * 2;
                ldsm_x4(af[mi], st + off);
            }
#pragma unroll
            for (int np = 0; np < 4; np++) {
                uint32_t off = (uint32_t)(wn * 64 + np * 16 + lr) * GPB + (ks * 16 + lk) * 2;
                uint32_t bf[4];
                ldsm_x4(bf, st + 18432u + off);
#pragma unroll
                for (int mi = 0; mi < 2; mi++) {
                    mma_f16(acc[mi][2 * np],     af[mi], bf[0], bf[2]);
                    mma_f16(acc[mi][2 * np + 1], af[mi], bf[1], bf[3]);
                }
            }
        }
    }

#pragma unroll
    for (int mi = 0; mi < 2; mi++) {
        int row = m0 + wm * 32 + mi * 16 + (lane >> 2);
#pragma unroll
        for (int nj = 0; nj < 8; nj++) {
            int col = n0 + wn * 64 + nj * 8 + (lane & 3) * 2;
            float b0 = bias[col], b1 = bias[col + 1];
            *(float2*)(Cf + (size_t)row * DMODEL + col) =
                make_float2(acc[mi][nj][0] + b0, acc[mi][nj][1] + b1);
            *(float2*)(Cf + (size_t)(row + 8) * DMODEL + col) =
                make_float2(acc[mi][nj][2] + b0, acc[mi][nj][3] + b1);
        }
    }
}

// ================= HMMA fp16 flash attention (R15 best: 64-row, 4 CTA/SM) ===
#define FL_SMEM  (46080 + 384)   // 46464
#define NKT (NTOK / 64)          // 32

__global__ __launch_bounds__(128, 4)
void flash_mma_kernel(const __half* __restrict__ Q, const __half* __restrict__ K,
                      const __half* __restrict__ V, const __half* __restrict__ pb,
                      __half* __restrict__ C) {
    extern __shared__ __align__(16) char sm[];
    const uint32_t sb = smem_u32(sm);
    const int tid = threadIdx.x, lane = tid & 31, wid = tid >> 5;
    const int qt = blockIdx.x, hh = blockIdx.y, b = blockIdx.z;
    const int rq0 = b * NTOK + qt * 64;

    auto load_kv = [&](int stage, int kt) {
        uint32_t st = sb + 9216 + stage * 18432;
        int rk0 = b * NTOK + kt * 64;
#pragma unroll
        for (int t = 0; t < 4; t++) {
            int u = tid + t * 128;
            int r = u >> 3, s = u & 7;
            size_t ga = (size_t)(rk0 + r) * DMODEL + hh * HD + s * 8;
            uint32_t d = (uint32_t)(r * GPB + s * 16);
            cp16(st + d,         K + ga);
            cp16(st + 9216 + d,  V + ga);
        }
        if (tid < 8)
            cp16(sb + 46080 + stage * 128 + tid * 16, pb + rk0 + tid * 8);
    };

#pragma unroll
    for (int t = 0; t < 4; t++) {
        int u = tid + t * 128;
        int r = u >> 3, s = u & 7;
        cp16(sb + (uint32_t)(r * GPB + s * 16),
             Q + (size_t)(rq0 + r) * DMODEL + hh * HD + s * 8);
    }
    load_kv(0, 0);
    CP_COMMIT();

    const int lr = (lane & 7) + ((lane >> 3) & 1) * 8;
    const int lk = (lane >> 4) * 8;

    uint32_t qf[4][4];
    float o[8][4];
#pragma unroll
    for (int j = 0; j < 8; j++)
#pragma unroll
        for (int q = 0; q < 4; q++) o[j][q] = 0.0f;
    float osum[4] = {0.0f, 0.0f, 0.0f, 0.0f};

    for (int kt = 0; kt < NKT; kt++) {
        const int cur = kt & 1;
        CP_WAIT0();
        __syncthreads();
        if (kt == 0) {
#pragma unroll
            for (int ks = 0; ks < 4; ks++) {
                uint32_t qoff = (uint32_t)(wid * 16 + lr) * GPB + (ks * 16 + lk) * 2;
                ldsm_x4(qf[ks], sb + qoff);
            }
        }
        if (kt + 1 < NKT) {
            load_kv(cur ^ 1, kt + 1);
            CP_COMMIT();
        }
        const uint32_t st = sb + 9216 + cur * 18432;

        float s[8][4];
#pragma unroll
        for (int j = 0; j < 8; j++)
#pragma unroll
            for (int q = 0; q < 4; q++) s[j][q] = 0.0f;

#pragma unroll
        for (int ks = 0; ks < 4; ks++) {
#pragma unroll
            for (int np = 0; np < 4; np++) {
                uint32_t off = (uint32_t)(np * 16 + lr) * GPB + (ks * 16 + lk) * 2;
                uint32_t bf[4];
                ldsm_x4(bf, st + off);
                mma_f16(s[2 * np],     qf[ks], bf[0], bf[2]);
                mma_f16(s[2 * np + 1], qf[ks], bf[1], bf[3]);
            }
        }

        const uint32_t* pbp = (const uint32_t*)(sm + 46080 + cur * 128);
        uint32_t sp0[8], sp1[8];
#pragma unroll
        for (int j = 0; j < 8; j++) {
            uint32_t pbh2 = pbp[j * 4 + (lane & 3)];
            sp0[j] = hex2(hadd2(pack2h(s[j][0], s[j][1]), pbh2));
            sp1[j] = hex2(hadd2(pack2h(s[j][2], s[j][3]), pbh2));
        }

#pragma unroll
        for (int ks = 0; ks < 4; ks++) {
            uint32_t ap[4] = {sp0[2 * ks], sp1[2 * ks], sp0[2 * ks + 1], sp1[2 * ks + 1]};
            mma_f16(osum, ap, ONES_H2, ONES_H2);
#pragma unroll
            for (int np = 0; np < 4; np++) {
                uint32_t off = (uint32_t)(ks * 16 + lr) * GPB + (np * 16 + lk) * 2;
                uint32_t vf[4];
                ldsm_x4t(vf, st + 9216u + off);
                mma_f16(o[2 * np],     ap, vf[0], vf[1]);
                mma_f16(o[2 * np + 1], ap, vf[2], vf[3]);
            }
        }
    }

    float inv0 = 1.0f / osum[0], inv1 = 1.0f / osum[2];
    int row = rq0 + wid * 16 + (lane >> 2);
#pragma unroll
    for (int j = 0; j < 8; j++) {
        int col = hh * HD + j * 8 + (lane & 3) * 2;
        *(uint32_t*)(C + (size_t)row * DMODEL + col)       = pack2h(o[j][0] * inv0, o[j][1] * inv0);
        *(uint32_t*)(C + (size_t)(row + 8) * DMODEL + col) = pack2h(o[j][2] * inv1, o[j][3] * inv1);
    }
}

// ---------------- launch ----------------------------------------------------
extern "C" void kernel_launch(void* const* d_in, const int* in_sizes, int n_in,
                              void* d_out, int out_size) {
    const float* h     = (const float*)d_in[0];
    const float* probs = (const float*)d_in[1];
    const float* Wq    = (const float*)d_in[2];
    const float* bq    = (const float*)d_in[3];
    const float* Wk    = (const float*)d_in[4];
    const float* bk    = (const float*)d_in[5];
    const float* Wv    = (const float*)d_in[6];
    const float* bv    = (const float*)d_in[7];
    const float* Wo    = (const float*)d_in[8];
    const float* bo    = (const float*)d_in[9];
    const float* pscal = (const float*)d_in[10];
    float* out = (float*)d_out;

    __half *hpe, *w, *qkv, *ctx, *pb;
    float *b3;
    cudaGetSymbolAddress((void**)&hpe, g_hpe);
    cudaGetSymbolAddress((void**)&w,   g_w);
    cudaGetSymbolAddress((void**)&qkv, g_qkv);
    cudaGetSymbolAddress((void**)&ctx, g_ctx);
    cudaGetSymbolAddress((void**)&pb,  g_pb);
    cudaGetSymbolAddress((void**)&b3,  g_bias3);

    cudaFuncSetAttribute(gemm_qkv_kernel,
                         cudaFuncAttributeMaxDynamicSharedMemorySize, GQ_SMEM);
    cudaFuncSetAttribute(gemm_out_kernel,
                         cudaFuncAttributeMaxDynamicSharedMemorySize, GO_SMEM);
    cudaFuncSetAttribute(flash_mma_kernel,
                         cudaFuncAttributeMaxDynamicSharedMemorySize, FL_SMEM);
    // Max smem carveout so 4 CTAs/SM actually fit (default split can cap at ~3)
    cudaFuncSetAttribute(gemm_qkv_kernel,
                         cudaFuncAttributePreferredSharedMemoryCarveout, 100);
    cudaFuncSetAttribute(flash_mma_kernel,
                         cudaFuncAttributePreferredSharedMemoryCarveout, 100);

    // 1. fully merged prep
    prep_kernel<<<PREP_GRID, 256>>>(h, probs, pscal, bq, bk, bv,
                                    Wq, Wk, Wv, Wo, hpe, w, pb, b3);

    // 2. fused QKV projection: 64x128 tiles, 4 CTA/SM
    const size_t QKV = (size_t)MROWS * DMODEL;
    dim3 qkvgrid(3 * DMODEL / 128, MROWS / 64);     // (24, 64)
    gemm_qkv_kernel<<<qkvgrid, 128, GQ_SMEM>>>(hpe, w, b3, qkv);

    // 3. flash attention
    dim3 fgrid(NTOK / 64, HEADS, BATCH);            // (32, 16, 2)
    flash_mma_kernel<<<fgrid, 128, FL_SMEM>>>(qkv, qkv + QKV, qkv + 2 * QKV, pb, ctx);

    // 4. output projection: 128x128 tiles, 2 CTA/SM (single wave)
    dim3 ogrid(DMODEL / 128, MROWS / 128);          // (8, 32)
    gemm_out_kernel<<<ogrid, 256, GO_SMEM>>>(ctx, w + 3 * WSZ, bo, out);
}